// round 6
// baseline (speedup 1.0000x reference)
#include <cuda_runtime.h>
#include <cuda_bf16.h>

typedef unsigned long long u64;
typedef unsigned int u32;

// ===========================================================================
// PTX helpers — family-portable only (.target sm_103): mma.sync bf16 (HMMA),
// ldmatrix, cp.async. No tcgen05/TMEM (rejected by compute_103 virtual arch).
// ===========================================================================
__device__ __forceinline__ u64 ffma2(u64 a, u64 b, u64 c) {
    asm("fma.rn.f32x2 %0, %1, %2, %0;" : "+l"(c) : "l"(a), "l"(b));
    return c;
}
__device__ __forceinline__ u64 dup2(float x) {
    u64 r; unsigned xi = __float_as_uint(x);
    asm("mov.b64 %0, {%1, %1};" : "=l"(r) : "r"(xi));
    return r;
}
__device__ __forceinline__ float2 unpk(u64 v) {
    unsigned lo, hi;
    asm("mov.b64 {%0, %1}, %2;" : "=r"(lo), "=r"(hi) : "l"(v));
    return make_float2(__uint_as_float(lo), __uint_as_float(hi));
}
__device__ __forceinline__ u32 smem_u32(const void* p) {
    u32 a;
    asm("{ .reg .u64 t; cvta.to.shared.u64 t, %1; cvt.u32.u64 %0, t; }" : "=r"(a) : "l"(p));
    return a;
}
__device__ __forceinline__ void ldsm4(u32 addr, u32 r[4]) {
    asm volatile("ldmatrix.sync.aligned.m8n8.x4.shared.b16 {%0,%1,%2,%3}, [%4];"
                 : "=r"(r[0]), "=r"(r[1]), "=r"(r[2]), "=r"(r[3]) : "r"(addr));
}
__device__ __forceinline__ void mma16816(float d[4], const u32 a[4], u32 b0, u32 b1) {
    asm volatile(
        "mma.sync.aligned.m16n8k16.row.col.f32.bf16.bf16.f32 "
        "{%0,%1,%2,%3}, {%4,%5,%6,%7}, {%8,%9}, {%0,%1,%2,%3};"
        : "+f"(d[0]), "+f"(d[1]), "+f"(d[2]), "+f"(d[3])
        : "r"(a[0]), "r"(a[1]), "r"(a[2]), "r"(a[3]), "r"(b0), "r"(b1));
}
#define CPASYNC(s, g) \
    asm volatile("cp.async.ca.shared.global [%0], [%1], 16;" :: "r"(s), "l"(g))
#define CPCOMMIT() asm volatile("cp.async.commit_group;" ::: "memory")
#define CPWAIT(n)  asm volatile("cp.async.wait_group %0;" :: "n"(n) : "memory")

// ===========================================================================
// Scratch (__device__ globals)
//   g_xg : PERMUTED gate preacts: xgp[cta 128][row 65536][slot 32] fp32
//          slot = q*8 + r for CTA's 8 units (q = gate i/f/g/o)
//   g_c  : cell state, PERMUTED: [cta 128][b 128][unit 8]
// ===========================================================================
__device__ float g_xg[268435456ULL];              // 128 * 65536 * 32
__device__ float g_h [67108864ULL];               // [65536][1024] fp32
__device__ float g_c [131072];                    // [128][128][8]
__device__ __nv_bfloat16 g_whh_hi[4194304];       // permuted W_hh hi [4096][1024]
__device__ __nv_bfloat16 g_whh_lo[4194304];
__device__ __nv_bfloat16 g_wih_hi[4194304];       // W_ih hi [4096][K]
__device__ __nv_bfloat16 g_wih_lo[4194304];
__device__ __nv_bfloat16 g_in_hi[4194304];        // input planes [65536][64]
__device__ __nv_bfloat16 g_in_lo[4194304];
__device__ __nv_bfloat16 g_hs_hi[67108864ULL];    // hseq planes [65536][1024]
__device__ __nv_bfloat16 g_hs_lo[67108864ULL];

__device__ unsigned g_bar_count = 0;
__device__ volatile unsigned g_bar_gen = 0;

__device__ __forceinline__ void grid_barrier(int nblocks) {
    __syncthreads();
    if (threadIdx.x == 0) {
        __threadfence();
        unsigned my_gen = g_bar_gen;
        if (atomicAdd(&g_bar_count, 1) == (unsigned)(nblocks - 1)) {
            g_bar_count = 0;
            __threadfence();
            g_bar_gen = my_gen + 1;
        } else {
            while (g_bar_gen == my_gen) { }
            __threadfence();
        }
    }
    __syncthreads();
}

// ===========================================================================
// split_plane: fp32 -> bf16 hi + lo residual. Grid = nelems/1024.
// ===========================================================================
__global__ void __launch_bounds__(256)
split_plane(const float* __restrict__ src, __nv_bfloat16* __restrict__ hi,
            __nv_bfloat16* __restrict__ lo)
{
    size_t i4 = (size_t)blockIdx.x * 256 + threadIdx.x;
    float4 v = ((const float4*)src)[i4];
    float xs[4] = {v.x, v.y, v.z, v.w};
    __nv_bfloat16 h[4], l[4];
#pragma unroll
    for (int e = 0; e < 4; e++) {
        h[e] = __float2bfloat16(xs[e]);
        l[e] = __float2bfloat16(xs[e] - __bfloat162float(h[e]));
    }
    __nv_bfloat162* hp = (__nv_bfloat162*)(hi + i4 * 4);
    __nv_bfloat162* lp = (__nv_bfloat162*)(lo + i4 * 4);
    hp[0] = __nv_bfloat162(h[0], h[1]); hp[1] = __nv_bfloat162(h[2], h[3]);
    lp[0] = __nv_bfloat162(l[0], l[1]); lp[1] = __nv_bfloat162(l[2], l[3]);
}

// ===========================================================================
// split_w: W_hh split + permute. out row = cta*32 + q*8 + r <- W row
// (cta*8 + r + q*1024).
// ===========================================================================
__global__ void __launch_bounds__(256)
split_w(const float* __restrict__ W, __nv_bfloat16* __restrict__ hi,
        __nv_bfloat16* __restrict__ lo)
{
    int orow = blockIdx.x;
    int cta = orow >> 5, cc = orow & 31;
    int q = cc >> 3, r = cc & 7;
    int wrow = cta * 8 + r + q * 1024;
    float4 v = ((const float4*)(W + (size_t)wrow * 1024))[threadIdx.x];
    size_t o = (size_t)orow * 1024 + threadIdx.x * 4;
    float xs[4] = {v.x, v.y, v.z, v.w};
#pragma unroll
    for (int e = 0; e < 4; e++) {
        __nv_bfloat16 h = __float2bfloat16(xs[e]);
        hi[o + e] = h;
        lo[o + e] = __float2bfloat16(xs[e] - __bfloat162float(h));
    }
}

// ===========================================================================
// SIMT f32x2 GEMM (small FC only): C[M,N] = A[M,K]@W[N,K]^T + b1(+b2)
// ===========================================================================
__global__ void __launch_bounds__(256)
gemm_bias(const float* __restrict__ A, const float* __restrict__ W,
          const float* __restrict__ b1, const float* __restrict__ b2,
          float* __restrict__ C, int N, int K)
{
    __shared__ float As[16 * 128];
    __shared__ float Ws[16 * 64];

    const int tid = threadIdx.x;
    const size_t m0 = (size_t)blockIdx.y * 128;
    const int n0 = blockIdx.x * 64;
    const int tm0 = (tid >> 4) * 8;
    const int tn0 = (tid & 15) * 4;

    u64 acc[4][4];
#pragma unroll
    for (int i = 0; i < 4; i++)
#pragma unroll
        for (int j = 0; j < 4; j++) acc[i][j] = 0ULL;

    const int lm  = tid >> 2;
    const int lkq = (tid & 3) * 4;

    for (int k0 = 0; k0 < K; k0 += 16) {
#pragma unroll
        for (int p = 0; p < 2; p++) {
            int m = lm + p * 64;
            float4 v = *(const float4*)(A + (m0 + m) * (size_t)K + k0 + lkq);
            As[(lkq + 0) * 128 + m] = v.x;
            As[(lkq + 1) * 128 + m] = v.y;
            As[(lkq + 2) * 128 + m] = v.z;
            As[(lkq + 3) * 128 + m] = v.w;
        }
        {
            float4 v = *(const float4*)(W + (size_t)(n0 + lm) * K + k0 + lkq);
            Ws[(lkq + 0) * 64 + lm] = v.x;
            Ws[(lkq + 1) * 64 + lm] = v.y;
            Ws[(lkq + 2) * 64 + lm] = v.z;
            Ws[(lkq + 3) * 64 + lm] = v.w;
        }
        __syncthreads();

#pragma unroll
        for (int k = 0; k < 16; k++) {
            u64 a0 = *(const u64*)(As + k * 128 + tm0 + 0);
            u64 a1 = *(const u64*)(As + k * 128 + tm0 + 2);
            u64 a2 = *(const u64*)(As + k * 128 + tm0 + 4);
            u64 a3 = *(const u64*)(As + k * 128 + tm0 + 6);
            float4 w = *(const float4*)(Ws + k * 64 + tn0);
            u64 w0 = dup2(w.x), w1 = dup2(w.y), w2 = dup2(w.z), w3 = dup2(w.w);
            acc[0][0] = ffma2(a0, w0, acc[0][0]); acc[0][1] = ffma2(a0, w1, acc[0][1]);
            acc[0][2] = ffma2(a0, w2, acc[0][2]); acc[0][3] = ffma2(a0, w3, acc[0][3]);
            acc[1][0] = ffma2(a1, w0, acc[1][0]); acc[1][1] = ffma2(a1, w1, acc[1][1]);
            acc[1][2] = ffma2(a1, w2, acc[1][2]); acc[1][3] = ffma2(a1, w3, acc[1][3]);
            acc[2][0] = ffma2(a2, w0, acc[2][0]); acc[2][1] = ffma2(a2, w1, acc[2][1]);
            acc[2][2] = ffma2(a2, w2, acc[2][2]); acc[2][3] = ffma2(a2, w3, acc[2][3]);
            acc[3][0] = ffma2(a3, w0, acc[3][0]); acc[3][1] = ffma2(a3, w1, acc[3][1]);
            acc[3][2] = ffma2(a3, w2, acc[3][2]); acc[3][3] = ffma2(a3, w3, acc[3][3]);
        }
        __syncthreads();
    }

#pragma unroll
    for (int j = 0; j < 4; j++) {
        int col = n0 + tn0 + j;
        float bias = b1[col] + (b2 ? b2[col] : 0.0f);
#pragma unroll
        for (int i = 0; i < 4; i++) {
            float2 v = unpk(acc[i][j]);
            size_t r = m0 + tm0 + 2 * i;
            C[r * (size_t)N + col]       = v.x + bias;
            C[(r + 1) * (size_t)N + col] = v.y + bias;
        }
    }
}

// ===========================================================================
// gemm_tc: xgp = A[M,K]@W[N,K]^T + b1 + b2, bf16 hi/lo 3-pass via mma.sync.
// Writes PERMUTED xg layout: xgp[cta][row][slot], cta=(col&1023)>>3,
// slot=(col>>10)*8 + (col&7).
// ===========================================================================
#define GT_PITCH 144
#define GT_PL    (128 * GT_PITCH)
#define GT_BUF   (4 * GT_PL)
#define GT_SMEM  (2 * GT_BUF)

__device__ __forceinline__ void gt_fill(u32 sb, const __nv_bfloat16* Ahi,
                                        const __nv_bfloat16* Alo,
                                        const __nv_bfloat16* Whi,
                                        const __nv_bfloat16* Wlo,
                                        size_t m0, int n0, int K, int k0, int tid)
{
#pragma unroll
    for (int i = 0; i < 8; i++) {
        int idx = tid + i * 256;
        int pl = idx >> 10, r2 = idx & 1023;
        int rr = r2 >> 3, ks = r2 & 7;
        const __nv_bfloat16* src = (pl ? Alo : Ahi) + (m0 + rr) * (size_t)K + k0 + ks * 8;
        CPASYNC(sb + pl * GT_PL + rr * GT_PITCH + ks * 16, src);
    }
#pragma unroll
    for (int i = 0; i < 8; i++) {
        int idx = tid + i * 256;
        int pl = idx >> 10, r2 = idx & 1023;
        int rr = r2 >> 3, ks = r2 & 7;
        const __nv_bfloat16* src = (pl ? Wlo : Whi) + (size_t)(n0 + rr) * K + k0 + ks * 8;
        CPASYNC(sb + 2 * GT_PL + pl * GT_PL + rr * GT_PITCH + ks * 16, src);
    }
}

__global__ void __launch_bounds__(256, 1)
gemm_tc(const __nv_bfloat16* __restrict__ Ahi, const __nv_bfloat16* __restrict__ Alo,
        const __nv_bfloat16* __restrict__ Whi, const __nv_bfloat16* __restrict__ Wlo,
        const float* __restrict__ b1, const float* __restrict__ b2,
        float* __restrict__ xgp, int N, int K)
{
    extern __shared__ char smem[];
    const u32 sbase = smem_u32(smem);
    const int tid = threadIdx.x;
    const int wid = tid >> 5, lane = tid & 31;
    const int wr = wid >> 2, wc = wid & 3;
    const size_t m0 = (size_t)blockIdx.y * 128;
    const int n0 = blockIdx.x * 128;
    const int NC = K / 64;

    float acc[4][4][4];
#pragma unroll
    for (int a = 0; a < 4; a++)
#pragma unroll
        for (int b = 0; b < 4; b++)
#pragma unroll
            for (int e = 0; e < 4; e++) acc[a][b][e] = 0.0f;

    const u32 a_r  = (u32)(lane & 15);
    const u32 a_c8 = (u32)((lane >> 4) << 3);
    const u32 b_r  = (u32)(((lane >> 4) << 3) + (lane & 7));
    const u32 b_c8 = (u32)(((lane >> 3) & 1) << 3);

    gt_fill(sbase, Ahi, Alo, Whi, Wlo, m0, n0, K, 0, tid);
    CPCOMMIT();

    for (int c = 0; c < NC; c++) {
        if (c + 1 < NC) {
            gt_fill(sbase + ((c + 1) & 1) * GT_BUF, Ahi, Alo, Whi, Wlo,
                    m0, n0, K, (c + 1) * 64, tid);
            CPCOMMIT();
            CPWAIT(1);
        } else {
            CPWAIT(0);
        }
        __syncthreads();

        const u32 ab = sbase + (c & 1) * GT_BUF;
#pragma unroll
        for (int kk = 0; kk < 4; kk++) {
            const u32 kc = (u32)(kk * 16);
            u32 baddr = ab + 2 * GT_PL + (wc * 32 + b_r) * GT_PITCH + (kc + b_c8) * 2;
            u32 bh0[4], bh1[4], bl0[4], bl1[4];
            ldsm4(baddr, bh0);
            ldsm4(baddr + 16 * GT_PITCH, bh1);
            ldsm4(baddr + GT_PL, bl0);
            ldsm4(baddr + GT_PL + 16 * GT_PITCH, bl1);
#pragma unroll
            for (int mb = 0; mb < 4; mb++) {
                u32 aaddr = ab + (wr * 64 + mb * 16 + a_r) * GT_PITCH + (kc + a_c8) * 2;
                u32 ah[4], al[4];
                ldsm4(aaddr, ah);
                ldsm4(aaddr + GT_PL, al);
                mma16816(acc[mb][0], ah, bh0[0], bh0[1]);
                mma16816(acc[mb][1], ah, bh0[2], bh0[3]);
                mma16816(acc[mb][2], ah, bh1[0], bh1[1]);
                mma16816(acc[mb][3], ah, bh1[2], bh1[3]);
                mma16816(acc[mb][0], ah, bl0[0], bl0[1]);
                mma16816(acc[mb][1], ah, bl0[2], bl0[3]);
                mma16816(acc[mb][2], ah, bl1[0], bl1[1]);
                mma16816(acc[mb][3], ah, bl1[2], bl1[3]);
                mma16816(acc[mb][0], al, bh0[0], bh0[1]);
                mma16816(acc[mb][1], al, bh0[2], bh0[3]);
                mma16816(acc[mb][2], al, bh1[0], bh1[1]);
                mma16816(acc[mb][3], al, bh1[2], bh1[3]);
            }
        }
        __syncthreads();
    }

    // epilogue: bias + permuted store (slot pairs adjacent -> float2 OK)
#pragma unroll
    for (int nb = 0; nb < 4; nb++) {
        int col = n0 + wc * 32 + nb * 8 + (lane & 3) * 2;
        float bs0 = b1[col]     + b2[col];
        float bs1 = b1[col + 1] + b2[col + 1];
        int q   = col >> 10;
        int cc  = col & 1023;
        int ctg = cc >> 3;
        int slot = q * 8 + (cc & 7);
        float* base = xgp + ((size_t)ctg << 21) + slot;
#pragma unroll
        for (int mb = 0; mb < 4; mb++) {
            size_t row = m0 + wr * 64 + mb * 16 + (lane >> 2);
            float2 v0 = make_float2(acc[mb][nb][0] + bs0, acc[mb][nb][1] + bs1);
            float2 v1 = make_float2(acc[mb][nb][2] + bs0, acc[mb][nb][3] + bs1);
            *(float2*)(base + row * 32)       = v0;
            *(float2*)(base + (row + 8) * 32) = v1;
        }
    }
}

// ===========================================================================
// Persistent recurrence. 128 CTAs x 256 threads. CTA owns 8 hidden units ->
// M=32 permuted gate rows, N=128 batch, K=1024 (16 x 64 chunks).
// W slice (hi+lo) RESIDENT in smem: [pl][chunk][32 rows][128B], 16B-column
// XOR swizzle (ks ^ (r&7)) keeps ldmatrix conflict-free at 128B pitch.
// B (h hi/lo) double-buffered via cp.async as before.
// smem map: [0,131072) Wres | [131072,204800) 2x B buf | [204800,221312) Gs
// ===========================================================================
#define WRES_PL  65536
#define WRES_CH  4096
#define BB_OFF   131072
#define BB_BUF   36864
#define BB_PL    18432
#define LS_PITCH 144
#define GS_OFF   204800
#define LS_SMEM  221312
#define LSTM_NBLK 128

__device__ __forceinline__ void ls_fill_b(u32 sb, const __nv_bfloat16* hhi,
                                          const __nv_bfloat16* hlo,
                                          int tp, int k0, int tid)
{
#pragma unroll
    for (int i = 0; i < 8; i++) {
        int idx = tid + i * 256;
        int pl = idx >> 10, r2 = idx & 1023;
        int rb = r2 >> 3, ks = r2 & 7;
        const __nv_bfloat16* src = (pl ? hlo : hhi) +
            ((size_t)rb * 512 + tp) * 1024 + k0 + ks * 8;
        CPASYNC(sb + pl * BB_PL + rb * LS_PITCH + ks * 16, src);
    }
}

__global__ void __launch_bounds__(256, 1)
lstm_mma(const float* __restrict__ xgp,         // [128][65536][32] permuted
         float* __restrict__ hseq,              // [65536][1024] fp32
         float* __restrict__ cst,               // [128][128][8] permuted
         const __nv_bfloat16* __restrict__ Whi, // permuted [4096][1024]
         const __nv_bfloat16* __restrict__ Wlo,
         __nv_bfloat16* __restrict__ hhi,       // [65536][1024]
         __nv_bfloat16* __restrict__ hlo)
{
    extern __shared__ char smem[];
    const u32 sbase = smem_u32(smem);
    float* Gs = (float*)(smem + GS_OFF);
    const int tid = threadIdx.x;
    const int wid = tid >> 5, lane = tid & 31;
    const int wr = wid >> 2, wc = wid & 3;
    const int cta = blockIdx.x;
    const int j0 = cta * 8;

    const u32 a_r  = (u32)(lane & 15);
    const u32 a_hi = (u32)(lane >> 4);           // 16B-half select
    const u32 a_sw = a_r & 7;                    // swizzle key
    const u32 a_row_off = (u32)((wr * 16 + a_r) * 128);
    const u32 b_r  = (u32)(((lane >> 4) << 3) + (lane & 7));
    const u32 b_c8 = (u32)(((lane >> 3) & 1) << 3);

    const int bB = tid >> 1;
    const int half = tid & 1;

    // --- prologue: load resident W slice (hi+lo, swizzled) ---
#pragma unroll
    for (int i = 0; i < 32; i++) {
        int idx = tid + i * 256;                 // 0..8191
        int pl = idx >> 12;
        int rem = idx & 4095;
        int c  = rem >> 8;
        int r2 = rem & 255;
        int rr = r2 >> 3, ks = r2 & 7;
        const __nv_bfloat16* src = (pl ? Wlo : Whi) +
            (size_t)(cta * 32 + rr) * 1024 + c * 64 + ks * 8;
        CPASYNC(sbase + pl * WRES_PL + c * WRES_CH + rr * 128 +
                ((u32)(ks ^ (rr & 7)) << 4), src);
    }
    CPCOMMIT();
    CPWAIT(0);
    __syncthreads();

    for (int t = 0; t < 512; t++) {
        if (t > 0) {
            float acc[4][4];
#pragma unroll
            for (int b = 0; b < 4; b++)
#pragma unroll
                for (int e = 0; e < 4; e++) acc[b][e] = 0.0f;

            ls_fill_b(sbase + BB_OFF, hhi, hlo, t - 1, 0, tid);
            CPCOMMIT();

            for (int c = 0; c < 16; c++) {
                if (c < 15) {
                    ls_fill_b(sbase + BB_OFF + ((c + 1) & 1) * BB_BUF,
                              hhi, hlo, t - 1, (c + 1) * 64, tid);
                    CPCOMMIT();
                    CPWAIT(1);
                } else {
                    CPWAIT(0);
                }
                __syncthreads();

                const u32 bb = sbase + BB_OFF + (c & 1) * BB_BUF;
                const u32 wb = sbase + c * WRES_CH;
#pragma unroll
                for (int kk = 0; kk < 4; kk++) {
                    const u32 kc = (u32)(kk * 16);
                    u32 au = ((u32)(2 * kk) + a_hi) ^ a_sw;
                    u32 aaddr = wb + a_row_off + (au << 4);
                    u32 ah[4], al[4];
                    ldsm4(aaddr, ah);
                    ldsm4(aaddr + WRES_PL, al);
                    u32 baddr = bb + (wc * 32 + b_r) * LS_PITCH + (kc + b_c8) * 2;
                    u32 bh0[4], bh1[4], bl0[4], bl1[4];
                    ldsm4(baddr, bh0);
                    ldsm4(baddr + 16 * LS_PITCH, bh1);
                    ldsm4(baddr + BB_PL, bl0);
                    ldsm4(baddr + BB_PL + 16 * LS_PITCH, bl1);
                    mma16816(acc[0], ah, bh0[0], bh0[1]);
                    mma16816(acc[1], ah, bh0[2], bh0[3]);
                    mma16816(acc[2], ah, bh1[0], bh1[1]);
                    mma16816(acc[3], ah, bh1[2], bh1[3]);
                    mma16816(acc[0], ah, bl0[0], bl0[1]);
                    mma16816(acc[1], ah, bl0[2], bl0[3]);
                    mma16816(acc[2], ah, bl1[0], bl1[1]);
                    mma16816(acc[3], ah, bl1[2], bl1[3]);
                    mma16816(acc[0], al, bh0[0], bh0[1]);
                    mma16816(acc[1], al, bh0[2], bh0[3]);
                    mma16816(acc[2], al, bh1[0], bh1[1]);
                    mma16816(acc[3], al, bh1[2], bh1[3]);
                }
                __syncthreads();
            }

            // spill accum to Gs[32 gate rows][128 batch] (pitch 129)
#pragma unroll
            for (int nb = 0; nb < 4; nb++) {
                int n = wc * 32 + nb * 8 + (lane & 3) * 2;
                int m = wr * 16 + (lane >> 2);
                Gs[m * 129 + n]           = acc[nb][0];
                Gs[m * 129 + n + 1]       = acc[nb][1];
                Gs[(m + 8) * 129 + n]     = acc[nb][2];
                Gs[(m + 8) * 129 + n + 1] = acc[nb][3];
            }
            __syncthreads();
        }

        // fused gate pass: thread = (batch bB, unit half)
        {
            size_t row = (size_t)bB * 512 + t;
            const float* xr = xgp + ((size_t)cta << 21) + row * 32 + half * 4;
            float4 xi = *(const float4*)(xr);
            float4 xf = *(const float4*)(xr + 8);
            float4 xq = *(const float4*)(xr + 16);
            float4 xo = *(const float4*)(xr + 24);
            float xia[4] = {xi.x, xi.y, xi.z, xi.w};
            float xfa[4] = {xf.x, xf.y, xf.z, xf.w};
            float xqa[4] = {xq.x, xq.y, xq.z, xq.w};
            float xoa[4] = {xo.x, xo.y, xo.z, xo.w};
            float cpa[4] = {0.f, 0.f, 0.f, 0.f};
            float ria[4] = {0.f, 0.f, 0.f, 0.f};
            float rfa[4] = {0.f, 0.f, 0.f, 0.f};
            float rqa[4] = {0.f, 0.f, 0.f, 0.f};
            float roa[4] = {0.f, 0.f, 0.f, 0.f};
            float* cslot = cst + cta * 1024 + bB * 8 + half * 4;
            if (t > 0) {
                float4 cv = *(const float4*)cslot;
                cpa[0] = cv.x; cpa[1] = cv.y; cpa[2] = cv.z; cpa[3] = cv.w;
#pragma unroll
                for (int r = 0; r < 4; r++) {
                    int u = half * 4 + r;
                    ria[r] = Gs[(0  + u) * 129 + bB];
                    rfa[r] = Gs[(8  + u) * 129 + bB];
                    rqa[r] = Gs[(16 + u) * 129 + bB];
                    roa[r] = Gs[(24 + u) * 129 + bB];
                }
            }
            float hva[4], cna[4];
#pragma unroll
            for (int r = 0; r < 4; r++) {
                float ig = 1.0f / (1.0f + expf(-(ria[r] + xia[r])));
                float fg = 1.0f / (1.0f + expf(-(rfa[r] + xfa[r])));
                float gv = tanhf(rqa[r] + xqa[r]);
                float og = 1.0f / (1.0f + expf(-(roa[r] + xoa[r])));
                cna[r] = fg * cpa[r] + ig * gv;
                hva[r] = og * tanhf(cna[r]);
            }
            *(float4*)cslot = make_float4(cna[0], cna[1], cna[2], cna[3]);
            *(float4*)(hseq + row * 1024 + j0 + half * 4) =
                make_float4(hva[0], hva[1], hva[2], hva[3]);
            __nv_bfloat16 hb[4], lb[4];
#pragma unroll
            for (int r = 0; r < 4; r++) {
                hb[r] = __float2bfloat16(hva[r]);
                lb[r] = __float2bfloat16(hva[r] - __bfloat162float(hb[r]));
            }
            __nv_bfloat162* hp = (__nv_bfloat162*)(hhi + row * 1024 + j0 + half * 4);
            __nv_bfloat162* lp = (__nv_bfloat162*)(hlo + row * 1024 + j0 + half * 4);
            hp[0] = __nv_bfloat162(hb[0], hb[1]); hp[1] = __nv_bfloat162(hb[2], hb[3]);
            lp[0] = __nv_bfloat162(lb[0], lb[1]); lp[1] = __nv_bfloat162(lb[2], lb[3]);
        }

        grid_barrier(LSTM_NBLK);
    }
}

// ===========================================================================
// Launch sequence (10 nodes), graph-capturable, allocation-free.
// ===========================================================================
extern "C" void kernel_launch(void* const* d_in, const int* in_sizes, int n_in,
                              void* d_out, int out_size)
{
    const float* input = (const float*)d_in[0];
    const float* W_ih0 = (const float*)d_in[1];
    const float* W_hh0 = (const float*)d_in[2];
    const float* b_ih0 = (const float*)d_in[3];
    const float* b_hh0 = (const float*)d_in[4];
    const float* W_ih1 = (const float*)d_in[5];
    const float* W_hh1 = (const float*)d_in[6];
    const float* b_ih1 = (const float*)d_in[7];
    const float* b_hh1 = (const float*)d_in[8];
    const float* W_fc  = (const float*)d_in[9];
    const float* b_fc  = (const float*)d_in[10];
    float* out = (float*)d_out;

    float *xg, *h, *c;
    __nv_bfloat16 *whhhi, *whhlo, *wihhi, *wihlo, *inhi, *inlo, *hshi, *hslo;
    cudaGetSymbolAddress((void**)&xg,    g_xg);
    cudaGetSymbolAddress((void**)&h,     g_h);
    cudaGetSymbolAddress((void**)&c,     g_c);
    cudaGetSymbolAddress((void**)&whhhi, g_whh_hi);
    cudaGetSymbolAddress((void**)&whhlo, g_whh_lo);
    cudaGetSymbolAddress((void**)&wihhi, g_wih_hi);
    cudaGetSymbolAddress((void**)&wihlo, g_wih_lo);
    cudaGetSymbolAddress((void**)&inhi,  g_in_hi);
    cudaGetSymbolAddress((void**)&inlo,  g_in_lo);
    cudaGetSymbolAddress((void**)&hshi,  g_hs_hi);
    cudaGetSymbolAddress((void**)&hslo,  g_hs_lo);

    cudaFuncSetAttribute(gemm_tc,  cudaFuncAttributeMaxDynamicSharedMemorySize, GT_SMEM);
    cudaFuncSetAttribute(lstm_mma, cudaFuncAttributeMaxDynamicSharedMemorySize, LS_SMEM);

    // ---- Layer 0 ----
    split_plane<<<4096, 256>>>(input, inhi, inlo);
    split_plane<<<256, 256>>>(W_ih0, wihhi, wihlo);
    {
        dim3 g(4096 / 128, 65536 / 128);
        gemm_tc<<<g, 256, GT_SMEM>>>(inhi, inlo, wihhi, wihlo,
                                     b_ih0, b_hh0, xg, 4096, 64);
    }
    split_w<<<4096, 256>>>(W_hh0, whhhi, whhlo);
    lstm_mma<<<LSTM_NBLK, 256, LS_SMEM>>>(xg, h, c, whhhi, whhlo, hshi, hslo);

    // ---- Layer 1 ----
    split_plane<<<4096, 256>>>(W_ih1, wihhi, wihlo);
    {
        dim3 g(4096 / 128, 65536 / 128);
        gemm_tc<<<g, 256, GT_SMEM>>>(hshi, hslo, wihhi, wihlo,
                                     b_ih1, b_hh1, xg, 4096, 1024);
    }
    split_w<<<4096, 256>>>(W_hh1, whhhi, whhlo);
    lstm_mma<<<LSTM_NBLK, 256, LS_SMEM>>>(xg, h, c, whhhi, whhlo, hshi, hslo);

    // ---- FC (SIMT) ----
    dim3 gf(1, 512);
    gemm_bias<<<gf, 256>>>(h, W_fc, b_fc, nullptr, out, 64, 1024);
}

// round 7
// speedup vs baseline: 1.0253x; 1.0253x over previous
#include <cuda_runtime.h>
#include <cuda_bf16.h>

typedef unsigned long long u64;
typedef unsigned int u32;

// ===========================================================================
// PTX helpers — family-portable only (.target sm_103): mma.sync bf16 (HMMA),
// ldmatrix, cp.async. No tcgen05/TMEM (rejected by compute_103 virtual arch).
// ===========================================================================
__device__ __forceinline__ u64 ffma2(u64 a, u64 b, u64 c) {
    asm("fma.rn.f32x2 %0, %1, %2, %0;" : "+l"(c) : "l"(a), "l"(b));
    return c;
}
__device__ __forceinline__ u64 dup2(float x) {
    u64 r; unsigned xi = __float_as_uint(x);
    asm("mov.b64 %0, {%1, %1};" : "=l"(r) : "r"(xi));
    return r;
}
__device__ __forceinline__ float2 unpk(u64 v) {
    unsigned lo, hi;
    asm("mov.b64 {%0, %1}, %2;" : "=r"(lo), "=r"(hi) : "l"(v));
    return make_float2(__uint_as_float(lo), __uint_as_float(hi));
}
__device__ __forceinline__ u32 smem_u32(const void* p) {
    u32 a;
    asm("{ .reg .u64 t; cvta.to.shared.u64 t, %1; cvt.u32.u64 %0, t; }" : "=r"(a) : "l"(p));
    return a;
}
__device__ __forceinline__ void ldsm4(u32 addr, u32 r[4]) {
    asm volatile("ldmatrix.sync.aligned.m8n8.x4.shared.b16 {%0,%1,%2,%3}, [%4];"
                 : "=r"(r[0]), "=r"(r[1]), "=r"(r[2]), "=r"(r[3]) : "r"(addr));
}
__device__ __forceinline__ void mma16816(float d[4], const u32 a[4], u32 b0, u32 b1) {
    asm volatile(
        "mma.sync.aligned.m16n8k16.row.col.f32.bf16.bf16.f32 "
        "{%0,%1,%2,%3}, {%4,%5,%6,%7}, {%8,%9}, {%0,%1,%2,%3};"
        : "+f"(d[0]), "+f"(d[1]), "+f"(d[2]), "+f"(d[3])
        : "r"(a[0]), "r"(a[1]), "r"(a[2]), "r"(a[3]), "r"(b0), "r"(b1));
}
// 16B cp.async, L1-bypass (.cg)
#define CPASYNC(s, g) \
    asm volatile("cp.async.cg.shared.global [%0], [%1], 16;" :: "r"(s), "l"(g))
#define CPCOMMIT() asm volatile("cp.async.commit_group;" ::: "memory")
#define CPWAIT(n)  asm volatile("cp.async.wait_group %0;" :: "n"(n) : "memory")

// ===========================================================================
// Scratch (__device__ globals)
//   g_xg : PERMUTED gate preacts: xgp[cta 128][row 65536][slot 32] fp32
//          slot = q*8 + r for the CTA's 8 units (q = gate i/f/g/o)
//   g_c  : cell state, PERMUTED: [cta 128][b 128][unit 8]
// ===========================================================================
__device__ float g_xg[268435456ULL];              // 128 * 65536 * 32
__device__ float g_h [67108864ULL];               // [65536][1024] fp32
__device__ float g_c [131072];                    // [128][128][8]
__device__ __nv_bfloat16 g_whh0_hi[4194304];      // permuted W_hh0 hi [4096][1024]
__device__ __nv_bfloat16 g_whh0_lo[4194304];
__device__ __nv_bfloat16 g_whh1_hi[4194304];      // permuted W_hh1 hi
__device__ __nv_bfloat16 g_whh1_lo[4194304];
__device__ __nv_bfloat16 g_wih_hi[4194304];       // W_ih hi [4096][K]
__device__ __nv_bfloat16 g_wih_lo[4194304];
__device__ __nv_bfloat16 g_in_hi[4194304];        // input planes [65536][64]
__device__ __nv_bfloat16 g_in_lo[4194304];
__device__ __nv_bfloat16 g_hs_hi[67108864ULL];    // hseq planes [65536][1024]
__device__ __nv_bfloat16 g_hs_lo[67108864ULL];

__device__ unsigned g_bar_count = 0;
__device__ volatile unsigned g_bar_gen = 0;

__device__ __forceinline__ void grid_barrier(int nblocks) {
    __syncthreads();
    if (threadIdx.x == 0) {
        __threadfence();
        unsigned my_gen = g_bar_gen;
        if (atomicAdd(&g_bar_count, 1) == (unsigned)(nblocks - 1)) {
            g_bar_count = 0;
            __threadfence();
            g_bar_gen = my_gen + 1;
        } else {
            while (g_bar_gen == my_gen) { }
            __threadfence();
        }
    }
    __syncthreads();
}

// ===========================================================================
// split_plane: fp32 -> bf16 hi + lo residual. Grid = nelems/1024.
// ===========================================================================
__global__ void __launch_bounds__(256)
split_plane(const float* __restrict__ src, __nv_bfloat16* __restrict__ hi,
            __nv_bfloat16* __restrict__ lo)
{
    size_t i4 = (size_t)blockIdx.x * 256 + threadIdx.x;
    float4 v = ((const float4*)src)[i4];
    float xs[4] = {v.x, v.y, v.z, v.w};
    __nv_bfloat16 h[4], l[4];
#pragma unroll
    for (int e = 0; e < 4; e++) {
        h[e] = __float2bfloat16(xs[e]);
        l[e] = __float2bfloat16(xs[e] - __bfloat162float(h[e]));
    }
    __nv_bfloat162* hp = (__nv_bfloat162*)(hi + i4 * 4);
    __nv_bfloat162* lp = (__nv_bfloat162*)(lo + i4 * 4);
    hp[0] = __nv_bfloat162(h[0], h[1]); hp[1] = __nv_bfloat162(h[2], h[3]);
    lp[0] = __nv_bfloat162(l[0], l[1]); lp[1] = __nv_bfloat162(l[2], l[3]);
}

// ===========================================================================
// split_w: W_hh split + permute. out row = cta*32 + q*8 + r <- W row
// (cta*8 + r + q*1024).
// ===========================================================================
__global__ void __launch_bounds__(256)
split_w(const float* __restrict__ W, __nv_bfloat16* __restrict__ hi,
        __nv_bfloat16* __restrict__ lo)
{
    int orow = blockIdx.x;
    int cta = orow >> 5, cc = orow & 31;
    int q = cc >> 3, r = cc & 7;
    int wrow = cta * 8 + r + q * 1024;
    float4 v = ((const float4*)(W + (size_t)wrow * 1024))[threadIdx.x];
    size_t o = (size_t)orow * 1024 + threadIdx.x * 4;
    float xs[4] = {v.x, v.y, v.z, v.w};
#pragma unroll
    for (int e = 0; e < 4; e++) {
        __nv_bfloat16 h = __float2bfloat16(xs[e]);
        hi[o + e] = h;
        lo[o + e] = __float2bfloat16(xs[e] - __bfloat162float(h));
    }
}

// ===========================================================================
// SIMT f32x2 GEMM (small FC only): C[M,N] = A[M,K]@W[N,K]^T + b1(+b2)
// ===========================================================================
__global__ void __launch_bounds__(256)
gemm_bias(const float* __restrict__ A, const float* __restrict__ W,
          const float* __restrict__ b1, const float* __restrict__ b2,
          float* __restrict__ C, int N, int K)
{
    __shared__ float As[16 * 128];
    __shared__ float Ws[16 * 64];

    const int tid = threadIdx.x;
    const size_t m0 = (size_t)blockIdx.y * 128;
    const int n0 = blockIdx.x * 64;
    const int tm0 = (tid >> 4) * 8;
    const int tn0 = (tid & 15) * 4;

    u64 acc[4][4];
#pragma unroll
    for (int i = 0; i < 4; i++)
#pragma unroll
        for (int j = 0; j < 4; j++) acc[i][j] = 0ULL;

    const int lm  = tid >> 2;
    const int lkq = (tid & 3) * 4;

    for (int k0 = 0; k0 < K; k0 += 16) {
#pragma unroll
        for (int p = 0; p < 2; p++) {
            int m = lm + p * 64;
            float4 v = *(const float4*)(A + (m0 + m) * (size_t)K + k0 + lkq);
            As[(lkq + 0) * 128 + m] = v.x;
            As[(lkq + 1) * 128 + m] = v.y;
            As[(lkq + 2) * 128 + m] = v.z;
            As[(lkq + 3) * 128 + m] = v.w;
        }
        {
            float4 v = *(const float4*)(W + (size_t)(n0 + lm) * K + k0 + lkq);
            Ws[(lkq + 0) * 64 + lm] = v.x;
            Ws[(lkq + 1) * 64 + lm] = v.y;
            Ws[(lkq + 2) * 64 + lm] = v.z;
            Ws[(lkq + 3) * 64 + lm] = v.w;
        }
        __syncthreads();

#pragma unroll
        for (int k = 0; k < 16; k++) {
            u64 a0 = *(const u64*)(As + k * 128 + tm0 + 0);
            u64 a1 = *(const u64*)(As + k * 128 + tm0 + 2);
            u64 a2 = *(const u64*)(As + k * 128 + tm0 + 4);
            u64 a3 = *(const u64*)(As + k * 128 + tm0 + 6);
            float4 w = *(const float4*)(Ws + k * 64 + tn0);
            u64 w0 = dup2(w.x), w1 = dup2(w.y), w2 = dup2(w.z), w3 = dup2(w.w);
            acc[0][0] = ffma2(a0, w0, acc[0][0]); acc[0][1] = ffma2(a0, w1, acc[0][1]);
            acc[0][2] = ffma2(a0, w2, acc[0][2]); acc[0][3] = ffma2(a0, w3, acc[0][3]);
            acc[1][0] = ffma2(a1, w0, acc[1][0]); acc[1][1] = ffma2(a1, w1, acc[1][1]);
            acc[1][2] = ffma2(a1, w2, acc[1][2]); acc[1][3] = ffma2(a1, w3, acc[1][3]);
            acc[2][0] = ffma2(a2, w0, acc[2][0]); acc[2][1] = ffma2(a2, w1, acc[2][1]);
            acc[2][2] = ffma2(a2, w2, acc[2][2]); acc[2][3] = ffma2(a2, w3, acc[2][3]);
            acc[3][0] = ffma2(a3, w0, acc[3][0]); acc[3][1] = ffma2(a3, w1, acc[3][1]);
            acc[3][2] = ffma2(a3, w2, acc[3][2]); acc[3][3] = ffma2(a3, w3, acc[3][3]);
        }
        __syncthreads();
    }

#pragma unroll
    for (int j = 0; j < 4; j++) {
        int col = n0 + tn0 + j;
        float bias = b1[col] + (b2 ? b2[col] : 0.0f);
#pragma unroll
        for (int i = 0; i < 4; i++) {
            float2 v = unpk(acc[i][j]);
            size_t r = m0 + tm0 + 2 * i;
            C[r * (size_t)N + col]       = v.x + bias;
            C[(r + 1) * (size_t)N + col] = v.y + bias;
        }
    }
}

// ===========================================================================
// gemm_tc: xgp = A[M,K]@W[N,K]^T + b1 + b2, bf16 hi/lo 3-pass via mma.sync.
// Writes PERMUTED xg: xgp[cta][row][slot], cta=(col&1023)>>3,
// slot=(col>>10)*8 + (col&7).
// ===========================================================================
#define GT_PITCH 144
#define GT_PL    (128 * GT_PITCH)
#define GT_BUF   (4 * GT_PL)
#define GT_SMEM  (2 * GT_BUF)

__device__ __forceinline__ void gt_fill(u32 sb, const __nv_bfloat16* Ahi,
                                        const __nv_bfloat16* Alo,
                                        const __nv_bfloat16* Whi,
                                        const __nv_bfloat16* Wlo,
                                        size_t m0, int n0, int K, int k0, int tid)
{
#pragma unroll
    for (int i = 0; i < 8; i++) {
        int idx = tid + i * 256;
        int pl = idx >> 10, r2 = idx & 1023;
        int rr = r2 >> 3, ks = r2 & 7;
        const __nv_bfloat16* src = (pl ? Alo : Ahi) + (m0 + rr) * (size_t)K + k0 + ks * 8;
        CPASYNC(sb + pl * GT_PL + rr * GT_PITCH + ks * 16, src);
    }
#pragma unroll
    for (int i = 0; i < 8; i++) {
        int idx = tid + i * 256;
        int pl = idx >> 10, r2 = idx & 1023;
        int rr = r2 >> 3, ks = r2 & 7;
        const __nv_bfloat16* src = (pl ? Wlo : Whi) + (size_t)(n0 + rr) * K + k0 + ks * 8;
        CPASYNC(sb + 2 * GT_PL + pl * GT_PL + rr * GT_PITCH + ks * 16, src);
    }
}

__global__ void __launch_bounds__(256, 1)
gemm_tc(const __nv_bfloat16* __restrict__ Ahi, const __nv_bfloat16* __restrict__ Alo,
        const __nv_bfloat16* __restrict__ Whi, const __nv_bfloat16* __restrict__ Wlo,
        const float* __restrict__ b1, const float* __restrict__ b2,
        float* __restrict__ xgp, int N, int K)
{
    extern __shared__ char smem[];
    const u32 sbase = smem_u32(smem);
    const int tid = threadIdx.x;
    const int wid = tid >> 5, lane = tid & 31;
    const int wr = wid >> 2, wc = wid & 3;
    const size_t m0 = (size_t)blockIdx.y * 128;
    const int n0 = blockIdx.x * 128;
    const int NC = K / 64;

    float acc[4][4][4];
#pragma unroll
    for (int a = 0; a < 4; a++)
#pragma unroll
        for (int b = 0; b < 4; b++)
#pragma unroll
            for (int e = 0; e < 4; e++) acc[a][b][e] = 0.0f;

    const u32 a_r  = (u32)(lane & 15);
    const u32 a_c8 = (u32)((lane >> 4) << 3);
    const u32 b_r  = (u32)(((lane >> 4) << 3) + (lane & 7));
    const u32 b_c8 = (u32)(((lane >> 3) & 1) << 3);

    gt_fill(sbase, Ahi, Alo, Whi, Wlo, m0, n0, K, 0, tid);
    CPCOMMIT();

    for (int c = 0; c < NC; c++) {
        if (c + 1 < NC) {
            gt_fill(sbase + ((c + 1) & 1) * GT_BUF, Ahi, Alo, Whi, Wlo,
                    m0, n0, K, (c + 1) * 64, tid);
            CPCOMMIT();
            CPWAIT(1);
        } else {
            CPWAIT(0);
        }
        __syncthreads();

        const u32 ab = sbase + (c & 1) * GT_BUF;
#pragma unroll
        for (int kk = 0; kk < 4; kk++) {
            const u32 kc = (u32)(kk * 16);
            u32 baddr = ab + 2 * GT_PL + (wc * 32 + b_r) * GT_PITCH + (kc + b_c8) * 2;
            u32 bh0[4], bh1[4], bl0[4], bl1[4];
            ldsm4(baddr, bh0);
            ldsm4(baddr + 16 * GT_PITCH, bh1);
            ldsm4(baddr + GT_PL, bl0);
            ldsm4(baddr + GT_PL + 16 * GT_PITCH, bl1);
#pragma unroll
            for (int mb = 0; mb < 4; mb++) {
                u32 aaddr = ab + (wr * 64 + mb * 16 + a_r) * GT_PITCH + (kc + a_c8) * 2;
                u32 ah[4], al[4];
                ldsm4(aaddr, ah);
                ldsm4(aaddr + GT_PL, al);
                mma16816(acc[mb][0], ah, bh0[0], bh0[1]);
                mma16816(acc[mb][1], ah, bh0[2], bh0[3]);
                mma16816(acc[mb][2], ah, bh1[0], bh1[1]);
                mma16816(acc[mb][3], ah, bh1[2], bh1[3]);
                mma16816(acc[mb][0], ah, bl0[0], bl0[1]);
                mma16816(acc[mb][1], ah, bl0[2], bl0[3]);
                mma16816(acc[mb][2], ah, bl1[0], bl1[1]);
                mma16816(acc[mb][3], ah, bl1[2], bl1[3]);
                mma16816(acc[mb][0], al, bh0[0], bh0[1]);
                mma16816(acc[mb][1], al, bh0[2], bh0[3]);
                mma16816(acc[mb][2], al, bh1[0], bh1[1]);
                mma16816(acc[mb][3], al, bh1[2], bh1[3]);
            }
        }
        __syncthreads();
    }

    // epilogue: bias + permuted store (slot pairs adjacent -> float2 OK)
#pragma unroll
    for (int nb = 0; nb < 4; nb++) {
        int col = n0 + wc * 32 + nb * 8 + (lane & 3) * 2;
        float bs0 = b1[col]     + b2[col];
        float bs1 = b1[col + 1] + b2[col + 1];
        int q   = col >> 10;
        int cc  = col & 1023;
        int ctg = cc >> 3;
        int slot = q * 8 + (cc & 7);
        float* base = xgp + ((size_t)ctg << 21) + slot;
#pragma unroll
        for (int mb = 0; mb < 4; mb++) {
            size_t row = m0 + wr * 64 + mb * 16 + (lane >> 2);
            float2 v0 = make_float2(acc[mb][nb][0] + bs0, acc[mb][nb][1] + bs1);
            float2 v1 = make_float2(acc[mb][nb][2] + bs0, acc[mb][nb][3] + bs1);
            *(float2*)(base + row * 32)       = v0;
            *(float2*)(base + (row + 8) * 32) = v1;
        }
    }
}

// ===========================================================================
// Persistent recurrence (R5 structure: W + B both double-buffered, 108KB smem)
// 128 CTAs x 256 threads. CTA owns 8 hidden units -> M=32 permuted gate rows,
// N=128 batch, K=1024 (16 x 64 chunks). 3-pass bf16 hi/lo.
// Gate pass uses PERMUTED xgp / cst layouts (coalesced 128B reads).
// ===========================================================================
#define LS_PITCH 144
#define LS_APL   (32 * LS_PITCH)         // 4608
#define LS_BPL   (128 * LS_PITCH)        // 18432
#define LS_BUF   (2 * LS_APL + 2 * LS_BPL)   // 46080
#define LS_GS    (2 * LS_BUF)            // 92160
#define LS_SMEM  (LS_GS + 32 * 129 * 4)  // 108672
#define LSTM_NBLK 128

__device__ __forceinline__ void ls_fill(u32 sb, const __nv_bfloat16* Whi,
                                        const __nv_bfloat16* Wlo,
                                        const __nv_bfloat16* hhi,
                                        const __nv_bfloat16* hlo,
                                        int cta, int tp, int k0, int tid)
{
#pragma unroll
    for (int i = 0; i < 2; i++) {        // A (Wperm slice): 2 planes x 32 x 8
        int idx = tid + i * 256;
        int pl = idx >> 8, r2 = idx & 255;
        int rr = r2 >> 3, ks = r2 & 7;
        const __nv_bfloat16* src = (pl ? Wlo : Whi) +
            (size_t)(cta * 32 + rr) * 1024 + k0 + ks * 8;
        CPASYNC(sb + pl * LS_APL + rr * LS_PITCH + ks * 16, src);
    }
#pragma unroll
    for (int i = 0; i < 8; i++) {        // B (h planes): 2 planes x 128 x 8
        int idx = tid + i * 256;
        int pl = idx >> 10, r2 = idx & 1023;
        int rb = r2 >> 3, ks = r2 & 7;
        const __nv_bfloat16* src = (pl ? hlo : hhi) +
            ((size_t)rb * 512 + tp) * 1024 + k0 + ks * 8;
        CPASYNC(sb + 2 * LS_APL + pl * LS_BPL + rb * LS_PITCH + ks * 16, src);
    }
}

__global__ void __launch_bounds__(256, 1)
lstm_mma(const float* __restrict__ xgp,         // [128][65536][32] permuted
         float* __restrict__ hseq,              // [65536][1024] fp32
         float* __restrict__ cst,               // [128][128][8] permuted
         const __nv_bfloat16* __restrict__ Whi, // permuted [4096][1024]
         const __nv_bfloat16* __restrict__ Wlo,
         __nv_bfloat16* __restrict__ hhi,       // [65536][1024]
         __nv_bfloat16* __restrict__ hlo)
{
    extern __shared__ char smem[];
    const u32 sbase = smem_u32(smem);
    float* Gs = (float*)(smem + LS_GS);
    const int tid = threadIdx.x;
    const int wid = tid >> 5, lane = tid & 31;
    const int wr = wid >> 2, wc = wid & 3;
    const int cta = blockIdx.x;
    const int j0 = cta * 8;

    const u32 a_r  = (u32)(lane & 15);
    const u32 a_c8 = (u32)((lane >> 4) << 3);
    const u32 b_r  = (u32)(((lane >> 4) << 3) + (lane & 7));
    const u32 b_c8 = (u32)(((lane >> 3) & 1) << 3);

    const int bB = tid >> 1;             // gate-pass batch index
    const int half = tid & 1;            // unit half

    for (int t = 0; t < 512; t++) {
        if (t > 0) {
            float acc[4][4];
#pragma unroll
            for (int b = 0; b < 4; b++)
#pragma unroll
                for (int e = 0; e < 4; e++) acc[b][e] = 0.0f;

            ls_fill(sbase, Whi, Wlo, hhi, hlo, cta, t - 1, 0, tid);
            CPCOMMIT();

            for (int c = 0; c < 16; c++) {
                if (c < 15) {
                    ls_fill(sbase + ((c + 1) & 1) * LS_BUF, Whi, Wlo, hhi, hlo,
                            cta, t - 1, (c + 1) * 64, tid);
                    CPCOMMIT();
                    CPWAIT(1);
                } else {
                    CPWAIT(0);
                }
                __syncthreads();

                const u32 ab = sbase + (c & 1) * LS_BUF;
#pragma unroll
                for (int kk = 0; kk < 4; kk++) {
                    const u32 kc = (u32)(kk * 16);
                    u32 aaddr = ab + (wr * 16 + a_r) * LS_PITCH + (kc + a_c8) * 2;
                    u32 ah[4], al[4];
                    ldsm4(aaddr, ah);
                    ldsm4(aaddr + LS_APL, al);
                    u32 baddr = ab + 2 * LS_APL + (wc * 32 + b_r) * LS_PITCH + (kc + b_c8) * 2;
                    u32 bh0[4], bh1[4], bl0[4], bl1[4];
                    ldsm4(baddr, bh0);
                    ldsm4(baddr + 16 * LS_PITCH, bh1);
                    ldsm4(baddr + LS_BPL, bl0);
                    ldsm4(baddr + LS_BPL + 16 * LS_PITCH, bl1);
                    mma16816(acc[0], ah, bh0[0], bh0[1]);
                    mma16816(acc[1], ah, bh0[2], bh0[3]);
                    mma16816(acc[2], ah, bh1[0], bh1[1]);
                    mma16816(acc[3], ah, bh1[2], bh1[3]);
                    mma16816(acc[0], ah, bl0[0], bl0[1]);
                    mma16816(acc[1], ah, bl0[2], bl0[3]);
                    mma16816(acc[2], ah, bl1[0], bl1[1]);
                    mma16816(acc[3], ah, bl1[2], bl1[3]);
                    mma16816(acc[0], al, bh0[0], bh0[1]);
                    mma16816(acc[1], al, bh0[2], bh0[3]);
                    mma16816(acc[2], al, bh1[0], bh1[1]);
                    mma16816(acc[3], al, bh1[2], bh1[3]);
                }
                __syncthreads();
            }

            // spill accum to Gs[32 gate rows][128 batch] (pitch 129)
#pragma unroll
            for (int nb = 0; nb < 4; nb++) {
                int n = wc * 32 + nb * 8 + (lane & 3) * 2;
                int m = wr * 16 + (lane >> 2);
                Gs[m * 129 + n]           = acc[nb][0];
                Gs[m * 129 + n + 1]       = acc[nb][1];
                Gs[(m + 8) * 129 + n]     = acc[nb][2];
                Gs[(m + 8) * 129 + n + 1] = acc[nb][3];
            }
            __syncthreads();
        }

        // fused gate pass (permuted xgp/cst, coalesced 128B rows)
        {
            size_t row = (size_t)bB * 512 + t;
            const float* xr = xgp + ((size_t)cta << 21) + row * 32 + half * 4;
            float4 xi = *(const float4*)(xr);
            float4 xf = *(const float4*)(xr + 8);
            float4 xq = *(const float4*)(xr + 16);
            float4 xo = *(const float4*)(xr + 24);
            float xia[4] = {xi.x, xi.y, xi.z, xi.w};
            float xfa[4] = {xf.x, xf.y, xf.z, xf.w};
            float xqa[4] = {xq.x, xq.y, xq.z, xq.w};
            float xoa[4] = {xo.x, xo.y, xo.z, xo.w};
            float cpa[4] = {0.f, 0.f, 0.f, 0.f};
            float ria[4] = {0.f, 0.f, 0.f, 0.f};
            float rfa[4] = {0.f, 0.f, 0.f, 0.f};
            float rqa[4] = {0.f, 0.f, 0.f, 0.f};
            float roa[4] = {0.f, 0.f, 0.f, 0.f};
            float* cslot = cst + cta * 1024 + bB * 8 + half * 4;
            if (t > 0) {
                float4 cv = *(const float4*)cslot;
                cpa[0] = cv.x; cpa[1] = cv.y; cpa[2] = cv.z; cpa[3] = cv.w;
#pragma unroll
                for (int r = 0; r < 4; r++) {
                    int u = half * 4 + r;
                    ria[r] = Gs[(0  + u) * 129 + bB];
                    rfa[r] = Gs[(8  + u) * 129 + bB];
                    rqa[r] = Gs[(16 + u) * 129 + bB];
                    roa[r] = Gs[(24 + u) * 129 + bB];
                }
            }
            float hva[4], cna[4];
#pragma unroll
            for (int r = 0; r < 4; r++) {
                float ig = 1.0f / (1.0f + expf(-(ria[r] + xia[r])));
                float fg = 1.0f / (1.0f + expf(-(rfa[r] + xfa[r])));
                float gv = tanhf(rqa[r] + xqa[r]);
                float og = 1.0f / (1.0f + expf(-(roa[r] + xoa[r])));
                cna[r] = fg * cpa[r] + ig * gv;
                hva[r] = og * tanhf(cna[r]);
            }
            *(float4*)cslot = make_float4(cna[0], cna[1], cna[2], cna[3]);
            *(float4*)(hseq + row * 1024 + j0 + half * 4) =
                make_float4(hva[0], hva[1], hva[2], hva[3]);
            __nv_bfloat16 hb[4], lb[4];
#pragma unroll
            for (int r = 0; r < 4; r++) {
                hb[r] = __float2bfloat16(hva[r]);
                lb[r] = __float2bfloat16(hva[r] - __bfloat162float(hb[r]));
            }
            __nv_bfloat162* hp = (__nv_bfloat162*)(hhi + row * 1024 + j0 + half * 4);
            __nv_bfloat162* lp = (__nv_bfloat162*)(hlo + row * 1024 + j0 + half * 4);
            hp[0] = __nv_bfloat162(hb[0], hb[1]); hp[1] = __nv_bfloat162(hb[2], hb[3]);
            lp[0] = __nv_bfloat162(lb[0], lb[1]); lp[1] = __nv_bfloat162(lb[2], lb[3]);
        }

        grid_barrier(LSTM_NBLK);
    }
}

// ===========================================================================
// Launch sequence — prep kernels up-front so launch #6 = lstm_mma (layer 0),
// which is what ncu -s 5 -c 1 will profile. Graph-capturable, alloc-free.
// ===========================================================================
extern "C" void kernel_launch(void* const* d_in, const int* in_sizes, int n_in,
                              void* d_out, int out_size)
{
    const float* input = (const float*)d_in[0];
    const float* W_ih0 = (const float*)d_in[1];
    const float* W_hh0 = (const float*)d_in[2];
    const float* b_ih0 = (const float*)d_in[3];
    const float* b_hh0 = (const float*)d_in[4];
    const float* W_ih1 = (const float*)d_in[5];
    const float* W_hh1 = (const float*)d_in[6];
    const float* b_ih1 = (const float*)d_in[7];
    const float* b_hh1 = (const float*)d_in[8];
    const float* W_fc  = (const float*)d_in[9];
    const float* b_fc  = (const float*)d_in[10];
    float* out = (float*)d_out;

    float *xg, *h, *c;
    __nv_bfloat16 *whh0hi, *whh0lo, *whh1hi, *whh1lo;
    __nv_bfloat16 *wihhi, *wihlo, *inhi, *inlo, *hshi, *hslo;
    cudaGetSymbolAddress((void**)&xg,     g_xg);
    cudaGetSymbolAddress((void**)&h,      g_h);
    cudaGetSymbolAddress((void**)&c,      g_c);
    cudaGetSymbolAddress((void**)&whh0hi, g_whh0_hi);
    cudaGetSymbolAddress((void**)&whh0lo, g_whh0_lo);
    cudaGetSymbolAddress((void**)&whh1hi, g_whh1_hi);
    cudaGetSymbolAddress((void**)&whh1lo, g_whh1_lo);
    cudaGetSymbolAddress((void**)&wihhi,  g_wih_hi);
    cudaGetSymbolAddress((void**)&wihlo,  g_wih_lo);
    cudaGetSymbolAddress((void**)&inhi,   g_in_hi);
    cudaGetSymbolAddress((void**)&inlo,   g_in_lo);
    cudaGetSymbolAddress((void**)&hshi,   g_hs_hi);
    cudaGetSymbolAddress((void**)&hslo,   g_hs_lo);

    cudaFuncSetAttribute(gemm_tc,  cudaFuncAttributeMaxDynamicSharedMemorySize, GT_SMEM);
    cudaFuncSetAttribute(lstm_mma, cudaFuncAttributeMaxDynamicSharedMemorySize, LS_SMEM);

    // Prep (launches 1-4)
    split_plane<<<4096, 256>>>(input, inhi, inlo);        // #1
    split_plane<<<256, 256>>>(W_ih0, wihhi, wihlo);       // #2
    split_w<<<4096, 256>>>(W_hh0, whh0hi, whh0lo);        // #3
    split_w<<<4096, 256>>>(W_hh1, whh1hi, whh1lo);        // #4

    // Layer 0 (launches 5-6)
    {
        dim3 g(4096 / 128, 65536 / 128);
        gemm_tc<<<g, 256, GT_SMEM>>>(inhi, inlo, wihhi, wihlo,
                                     b_ih0, b_hh0, xg, 4096, 64);   // #5
    }
    lstm_mma<<<LSTM_NBLK, 256, LS_SMEM>>>(xg, h, c, whh0hi, whh0lo,
                                          hshi, hslo);              // #6 <- ncu
    // Layer 1 (launches 7-9)
    split_plane<<<4096, 256>>>(W_ih1, wihhi, wihlo);      // #7
    {
        dim3 g(4096 / 128, 65536 / 128);
        gemm_tc<<<g, 256, GT_SMEM>>>(hshi, hslo, wihhi, wihlo,
                                     b_ih1, b_hh1, xg, 4096, 1024); // #8
    }
    lstm_mma<<<LSTM_NBLK, 256, LS_SMEM>>>(xg, h, c, whh1hi, whh1lo,
                                          hshi, hslo);              // #9

    // FC (launch 10)
    dim3 gf(1, 512);
    gemm_bias<<<gf, 256>>>(h, W_fc, b_fc, nullptr, out, 64, 1024);  // #10
}

// round 8
// speedup vs baseline: 1.1036x; 1.0763x over previous
#include <cuda_runtime.h>
#include <cuda_bf16.h>

typedef unsigned long long u64;
typedef unsigned int u32;

// ===========================================================================
// PTX helpers — family-portable only (.target sm_103): mma.sync bf16 (HMMA),
// ldmatrix, cp.async. No tcgen05/TMEM (rejected by compute_103 virtual arch).
// ===========================================================================
__device__ __forceinline__ u64 ffma2(u64 a, u64 b, u64 c) {
    asm("fma.rn.f32x2 %0, %1, %2, %0;" : "+l"(c) : "l"(a), "l"(b));
    return c;
}
__device__ __forceinline__ u64 dup2(float x) {
    u64 r; unsigned xi = __float_as_uint(x);
    asm("mov.b64 %0, {%1, %1};" : "=l"(r) : "r"(xi));
    return r;
}
__device__ __forceinline__ float2 unpk(u64 v) {
    unsigned lo, hi;
    asm("mov.b64 {%0, %1}, %2;" : "=r"(lo), "=r"(hi) : "l"(v));
    return make_float2(__uint_as_float(lo), __uint_as_float(hi));
}
__device__ __forceinline__ u32 smem_u32(const void* p) {
    u32 a;
    asm("{ .reg .u64 t; cvta.to.shared.u64 t, %1; cvt.u32.u64 %0, t; }" : "=r"(a) : "l"(p));
    return a;
}
__device__ __forceinline__ void ldsm4(u32 addr, u32 r[4]) {
    asm volatile("ldmatrix.sync.aligned.m8n8.x4.shared.b16 {%0,%1,%2,%3}, [%4];"
                 : "=r"(r[0]), "=r"(r[1]), "=r"(r[2]), "=r"(r[3]) : "r"(addr));
}
__device__ __forceinline__ void mma16816(float d[4], const u32 a[4], u32 b0, u32 b1) {
    asm volatile(
        "mma.sync.aligned.m16n8k16.row.col.f32.bf16.bf16.f32 "
        "{%0,%1,%2,%3}, {%4,%5,%6,%7}, {%8,%9}, {%0,%1,%2,%3};"
        : "+f"(d[0]), "+f"(d[1]), "+f"(d[2]), "+f"(d[3])
        : "r"(a[0]), "r"(a[1]), "r"(a[2]), "r"(a[3]), "r"(b0), "r"(b1));
}
// .ca for read-only / write-once-read-once streams (R5 behavior)
#define CPASYNC(s, g) \
    asm volatile("cp.async.ca.shared.global [%0], [%1], 16;" :: "r"(s), "l"(g))
// .cg (L1 bypass) — REQUIRED for the partial buffer: its addresses are
// rewritten by other CTAs every step; a stale L1 line would corrupt silently.
#define CPASYNC_CG(s, g) \
    asm volatile("cp.async.cg.shared.global [%0], [%1], 16;" :: "r"(s), "l"(g))
#define CPCOMMIT() asm volatile("cp.async.commit_group;" ::: "memory")
#define CPWAIT(n)  asm volatile("cp.async.wait_group %0;" :: "n"(n) : "memory")

// ===========================================================================
// Scratch (__device__ globals)
// ===========================================================================
__device__ float g_xg[268435456ULL];              // [65536][4096] fp32
__device__ float g_h [67108864ULL];               // [65536][1024] fp32
__device__ float g_partial[2097152];              // Pg[k 4][m 32][row 128][b 128]
__device__ __nv_bfloat16 g_whh0_hi[4194304];      // permuted W_hh0 hi [4096][1024]
__device__ __nv_bfloat16 g_whh0_lo[4194304];
__device__ __nv_bfloat16 g_whh1_hi[4194304];
__device__ __nv_bfloat16 g_whh1_lo[4194304];
__device__ __nv_bfloat16 g_wih_hi[4194304];       // W_ih hi [4096][K]
__device__ __nv_bfloat16 g_wih_lo[4194304];
__device__ __nv_bfloat16 g_in_hi[4194304];        // input planes [65536][64]
__device__ __nv_bfloat16 g_in_lo[4194304];
__device__ __nv_bfloat16 g_hs_hi[67108864ULL];    // hseq planes [65536][1024]
__device__ __nv_bfloat16 g_hs_lo[67108864ULL];

__device__ unsigned g_bar_count = 0;
__device__ volatile unsigned g_bar_gen = 0;

__device__ __forceinline__ void grid_barrier(int nblocks) {
    __syncthreads();
    if (threadIdx.x == 0) {
        __threadfence();
        unsigned my_gen = g_bar_gen;
        if (atomicAdd(&g_bar_count, 1) == (unsigned)(nblocks - 1)) {
            g_bar_count = 0;
            __threadfence();
            g_bar_gen = my_gen + 1;
        } else {
            while (g_bar_gen == my_gen) { }
            __threadfence();
        }
    }
    __syncthreads();
}

// ===========================================================================
// split_plane: fp32 -> bf16 hi + lo residual. Grid = nelems/1024.
// ===========================================================================
__global__ void __launch_bounds__(256)
split_plane(const float* __restrict__ src, __nv_bfloat16* __restrict__ hi,
            __nv_bfloat16* __restrict__ lo)
{
    size_t i4 = (size_t)blockIdx.x * 256 + threadIdx.x;
    float4 v = ((const float4*)src)[i4];
    float xs[4] = {v.x, v.y, v.z, v.w};
    __nv_bfloat16 h[4], l[4];
#pragma unroll
    for (int e = 0; e < 4; e++) {
        h[e] = __float2bfloat16(xs[e]);
        l[e] = __float2bfloat16(xs[e] - __bfloat162float(h[e]));
    }
    __nv_bfloat162* hp = (__nv_bfloat162*)(hi + i4 * 4);
    __nv_bfloat162* lp = (__nv_bfloat162*)(lo + i4 * 4);
    hp[0] = __nv_bfloat162(h[0], h[1]); hp[1] = __nv_bfloat162(h[2], h[3]);
    lp[0] = __nv_bfloat162(l[0], l[1]); lp[1] = __nv_bfloat162(l[2], l[3]);
}

// ===========================================================================
// split_w32: W_hh split + permute for the K-split recurrence.
// out row = m*128 + q*32 + r  <-  W_hh row (m*32 + r + q*1024),
// m = unit-group 0..31 (32 units each), q = gate, r = unit-in-group.
// ===========================================================================
__global__ void __launch_bounds__(256)
split_w32(const float* __restrict__ W, __nv_bfloat16* __restrict__ hi,
          __nv_bfloat16* __restrict__ lo)
{
    int orow = blockIdx.x;                 // 0..4095
    int m = orow >> 7, rem = orow & 127;
    int q = rem >> 5, r = rem & 31;
    int wrow = m * 32 + r + q * 1024;
    float4 v = ((const float4*)(W + (size_t)wrow * 1024))[threadIdx.x];
    size_t o = (size_t)orow * 1024 + threadIdx.x * 4;
    float xs[4] = {v.x, v.y, v.z, v.w};
#pragma unroll
    for (int e = 0; e < 4; e++) {
        __nv_bfloat16 h = __float2bfloat16(xs[e]);
        hi[o + e] = h;
        lo[o + e] = __float2bfloat16(xs[e] - __bfloat162float(h));
    }
}

// ===========================================================================
// SIMT f32x2 GEMM (small FC only): C[M,N] = A[M,K]@W[N,K]^T + b1(+b2)
// ===========================================================================
__global__ void __launch_bounds__(256)
gemm_bias(const float* __restrict__ A, const float* __restrict__ W,
          const float* __restrict__ b1, const float* __restrict__ b2,
          float* __restrict__ C, int N, int K)
{
    __shared__ float As[16 * 128];
    __shared__ float Ws[16 * 64];

    const int tid = threadIdx.x;
    const size_t m0 = (size_t)blockIdx.y * 128;
    const int n0 = blockIdx.x * 64;
    const int tm0 = (tid >> 4) * 8;
    const int tn0 = (tid & 15) * 4;

    u64 acc[4][4];
#pragma unroll
    for (int i = 0; i < 4; i++)
#pragma unroll
        for (int j = 0; j < 4; j++) acc[i][j] = 0ULL;

    const int lm  = tid >> 2;
    const int lkq = (tid & 3) * 4;

    for (int k0 = 0; k0 < K; k0 += 16) {
#pragma unroll
        for (int p = 0; p < 2; p++) {
            int m = lm + p * 64;
            float4 v = *(const float4*)(A + (m0 + m) * (size_t)K + k0 + lkq);
            As[(lkq + 0) * 128 + m] = v.x;
            As[(lkq + 1) * 128 + m] = v.y;
            As[(lkq + 2) * 128 + m] = v.z;
            As[(lkq + 3) * 128 + m] = v.w;
        }
        {
            float4 v = *(const float4*)(W + (size_t)(n0 + lm) * K + k0 + lkq);
            Ws[(lkq + 0) * 64 + lm] = v.x;
            Ws[(lkq + 1) * 64 + lm] = v.y;
            Ws[(lkq + 2) * 64 + lm] = v.z;
            Ws[(lkq + 3) * 64 + lm] = v.w;
        }
        __syncthreads();

#pragma unroll
        for (int k = 0; k < 16; k++) {
            u64 a0 = *(const u64*)(As + k * 128 + tm0 + 0);
            u64 a1 = *(const u64*)(As + k * 128 + tm0 + 2);
            u64 a2 = *(const u64*)(As + k * 128 + tm0 + 4);
            u64 a3 = *(const u64*)(As + k * 128 + tm0 + 6);
            float4 w = *(const float4*)(Ws + k * 64 + tn0);
            u64 w0 = dup2(w.x), w1 = dup2(w.y), w2 = dup2(w.z), w3 = dup2(w.w);
            acc[0][0] = ffma2(a0, w0, acc[0][0]); acc[0][1] = ffma2(a0, w1, acc[0][1]);
            acc[0][2] = ffma2(a0, w2, acc[0][2]); acc[0][3] = ffma2(a0, w3, acc[0][3]);
            acc[1][0] = ffma2(a1, w0, acc[1][0]); acc[1][1] = ffma2(a1, w1, acc[1][1]);
            acc[1][2] = ffma2(a1, w2, acc[1][2]); acc[1][3] = ffma2(a1, w3, acc[1][3]);
            acc[2][0] = ffma2(a2, w0, acc[2][0]); acc[2][1] = ffma2(a2, w1, acc[2][1]);
            acc[2][2] = ffma2(a2, w2, acc[2][2]); acc[2][3] = ffma2(a2, w3, acc[2][3]);
            acc[3][0] = ffma2(a3, w0, acc[3][0]); acc[3][1] = ffma2(a3, w1, acc[3][1]);
            acc[3][2] = ffma2(a3, w2, acc[3][2]); acc[3][3] = ffma2(a3, w3, acc[3][3]);
        }
        __syncthreads();
    }

#pragma unroll
    for (int j = 0; j < 4; j++) {
        int col = n0 + tn0 + j;
        float bias = b1[col] + (b2 ? b2[col] : 0.0f);
#pragma unroll
        for (int i = 0; i < 4; i++) {
            float2 v = unpk(acc[i][j]);
            size_t r = m0 + tm0 + 2 * i;
            C[r * (size_t)N + col]       = v.x + bias;
            C[(r + 1) * (size_t)N + col] = v.y + bias;
        }
    }
}

// ===========================================================================
// gemm_tc (R5 version): C[M,N] = A[M,K]@W[N,K]^T + b1 + b2, bf16 hi/lo
// 3-pass via mma.sync. Plain C store.
// ===========================================================================
#define GT_PITCH 144
#define GT_PL    (128 * GT_PITCH)
#define GT_BUF   (4 * GT_PL)
#define GT_SMEM  (2 * GT_BUF)

__device__ __forceinline__ void gt_fill(u32 sb, const __nv_bfloat16* Ahi,
                                        const __nv_bfloat16* Alo,
                                        const __nv_bfloat16* Whi,
                                        const __nv_bfloat16* Wlo,
                                        size_t m0, int n0, int K, int k0, int tid)
{
#pragma unroll
    for (int i = 0; i < 8; i++) {
        int idx = tid + i * 256;
        int pl = idx >> 10, r2 = idx & 1023;
        int rr = r2 >> 3, ks = r2 & 7;
        const __nv_bfloat16* src = (pl ? Alo : Ahi) + (m0 + rr) * (size_t)K + k0 + ks * 8;
        CPASYNC(sb + pl * GT_PL + rr * GT_PITCH + ks * 16, src);
    }
#pragma unroll
    for (int i = 0; i < 8; i++) {
        int idx = tid + i * 256;
        int pl = idx >> 10, r2 = idx & 1023;
        int rr = r2 >> 3, ks = r2 & 7;
        const __nv_bfloat16* src = (pl ? Wlo : Whi) + (size_t)(n0 + rr) * K + k0 + ks * 8;
        CPASYNC(sb + 2 * GT_PL + pl * GT_PL + rr * GT_PITCH + ks * 16, src);
    }
}

__global__ void __launch_bounds__(256, 1)
gemm_tc(const __nv_bfloat16* __restrict__ Ahi, const __nv_bfloat16* __restrict__ Alo,
        const __nv_bfloat16* __restrict__ Whi, const __nv_bfloat16* __restrict__ Wlo,
        const float* __restrict__ b1, const float* __restrict__ b2,
        float* __restrict__ C, int N, int K)
{
    extern __shared__ char smem[];
    const u32 sbase = smem_u32(smem);
    const int tid = threadIdx.x;
    const int wid = tid >> 5, lane = tid & 31;
    const int wr = wid >> 2, wc = wid & 3;
    const size_t m0 = (size_t)blockIdx.y * 128;
    const int n0 = blockIdx.x * 128;
    const int NC = K / 64;

    float acc[4][4][4];
#pragma unroll
    for (int a = 0; a < 4; a++)
#pragma unroll
        for (int b = 0; b < 4; b++)
#pragma unroll
            for (int e = 0; e < 4; e++) acc[a][b][e] = 0.0f;

    const u32 a_r  = (u32)(lane & 15);
    const u32 a_c8 = (u32)((lane >> 4) << 3);
    const u32 b_r  = (u32)(((lane >> 4) << 3) + (lane & 7));
    const u32 b_c8 = (u32)(((lane >> 3) & 1) << 3);

    gt_fill(sbase, Ahi, Alo, Whi, Wlo, m0, n0, K, 0, tid);
    CPCOMMIT();

    for (int c = 0; c < NC; c++) {
        if (c + 1 < NC) {
            gt_fill(sbase + ((c + 1) & 1) * GT_BUF, Ahi, Alo, Whi, Wlo,
                    m0, n0, K, (c + 1) * 64, tid);
            CPCOMMIT();
            CPWAIT(1);
        } else {
            CPWAIT(0);
        }
        __syncthreads();

        const u32 ab = sbase + (c & 1) * GT_BUF;
#pragma unroll
        for (int kk = 0; kk < 4; kk++) {
            const u32 kc = (u32)(kk * 16);
            u32 baddr = ab + 2 * GT_PL + (wc * 32 + b_r) * GT_PITCH + (kc + b_c8) * 2;
            u32 bh0[4], bh1[4], bl0[4], bl1[4];
            ldsm4(baddr, bh0);
            ldsm4(baddr + 16 * GT_PITCH, bh1);
            ldsm4(baddr + GT_PL, bl0);
            ldsm4(baddr + GT_PL + 16 * GT_PITCH, bl1);
#pragma unroll
            for (int mb = 0; mb < 4; mb++) {
                u32 aaddr = ab + (wr * 64 + mb * 16 + a_r) * GT_PITCH + (kc + a_c8) * 2;
                u32 ah[4], al[4];
                ldsm4(aaddr, ah);
                ldsm4(aaddr + GT_PL, al);
                mma16816(acc[mb][0], ah, bh0[0], bh0[1]);
                mma16816(acc[mb][1], ah, bh0[2], bh0[3]);
                mma16816(acc[mb][2], ah, bh1[0], bh1[1]);
                mma16816(acc[mb][3], ah, bh1[2], bh1[3]);
                mma16816(acc[mb][0], ah, bl0[0], bl0[1]);
                mma16816(acc[mb][1], ah, bl0[2], bl0[3]);
                mma16816(acc[mb][2], ah, bl1[0], bl1[1]);
                mma16816(acc[mb][3], ah, bl1[2], bl1[3]);
                mma16816(acc[mb][0], al, bh0[0], bh0[1]);
                mma16816(acc[mb][1], al, bh0[2], bh0[3]);
                mma16816(acc[mb][2], al, bh1[0], bh1[1]);
                mma16816(acc[mb][3], al, bh1[2], bh1[3]);
            }
        }
        __syncthreads();
    }

#pragma unroll
    for (int nb = 0; nb < 4; nb++) {
        int col = n0 + wc * 32 + nb * 8 + (lane & 3) * 2;
        float bs0 = b1[col]     + b2[col];
        float bs1 = b1[col + 1] + b2[col + 1];
#pragma unroll
        for (int mb = 0; mb < 4; mb++) {
            size_t row = m0 + wr * 64 + mb * 16 + (lane >> 2);
            float2 v0 = make_float2(acc[mb][nb][0] + bs0, acc[mb][nb][1] + bs1);
            float2 v1 = make_float2(acc[mb][nb][2] + bs0, acc[mb][nb][3] + bs1);
            *(float2*)(C + row * (size_t)N + col)       = v0;
            *(float2*)(C + (row + 8) * (size_t)N + col) = v1;
        }
    }
}

// ===========================================================================
// Persistent K-split recurrence. 128 CTAs = (m 0..31) x (ks 0..3).
// CTA (m,ks): M=128 permuted gate rows (units m*32..+32), N=128 batch,
// K-quarter ks*256..+256 (4 chunks of 64). 3-pass bf16 hi/lo mma.
// Per step: mma -> partial Pg[ks][m] -> BARRIER -> stage 4 k-partials
// (cp.async.cg) + gate pass over (32 units x 32-batch quarter), c in smem
// -> BARRIER.
// smem: [0,147456) 2x(Ahi,Alo,Bhi,Blo) | [147456,221184) P_s 4x[128][36w]
//       | [221184,225792) c-state [32u][36w]
// ===========================================================================
#define LSB_PITCH 144
#define LSB_PL    (128 * LSB_PITCH)      // 18432
#define LSB_BUF   (4 * LSB_PL)           // 73728
#define PS_OFF    (2 * LSB_BUF)          // 147456
#define PS_K      18432                  // 128 rows x 144B (36 words)
#define CS_OFF    (PS_OFF + 4 * PS_K)    // 221184
#define LS_SMEM   (CS_OFF + 4608)        // 225792
#define LSTM_NBLK 128

__device__ __forceinline__ void ls_fill(u32 sb, const __nv_bfloat16* Whi,
                                        const __nv_bfloat16* Wlo,
                                        const __nv_bfloat16* hhi,
                                        const __nv_bfloat16* hlo,
                                        int m, int k0, int tp, int tid)
{
#pragma unroll
    for (int i = 0; i < 8; i++) {        // A = Wperm: 2 planes x 128 rows x 8
        int idx = tid + i * 256;
        int pl = idx >> 10, r2 = idx & 1023;
        int rr = r2 >> 3, seg = r2 & 7;
        const __nv_bfloat16* src = (pl ? Wlo : Whi) +
            (size_t)(m * 128 + rr) * 1024 + k0 + seg * 8;
        CPASYNC(sb + pl * LSB_PL + rr * LSB_PITCH + seg * 16, src);
    }
#pragma unroll
    for (int i = 0; i < 8; i++) {        // B = h planes: 2 x 128 batch x 8
        int idx = tid + i * 256;
        int pl = idx >> 10, r2 = idx & 1023;
        int rb = r2 >> 3, seg = r2 & 7;
        const __nv_bfloat16* src = (pl ? hlo : hhi) +
            ((size_t)rb * 512 + tp) * 1024 + k0 + seg * 8;
        CPASYNC(sb + 2 * LSB_PL + pl * LSB_PL + rb * LSB_PITCH + seg * 16, src);
    }
}

__global__ void __launch_bounds__(256, 1)
lstm_mma(const float* __restrict__ xg,          // [65536][4096]
         float* __restrict__ hseq,              // [65536][1024] fp32
         float* __restrict__ partial,           // Pg[4][32][128][128] fp32
         const __nv_bfloat16* __restrict__ Whi, // permuted [4096][1024]
         const __nv_bfloat16* __restrict__ Wlo,
         __nv_bfloat16* __restrict__ hhi,       // [65536][1024]
         __nv_bfloat16* __restrict__ hlo)
{
    extern __shared__ char smem[];
    const u32 sbase = smem_u32(smem);
    float* Ps = (float*)(smem + PS_OFF);
    float* cs = (float*)(smem + CS_OFF);
    const int tid = threadIdx.x;
    const int w = tid >> 5, lane = tid & 31;
    const int wr = w >> 2, wc = w & 3;
    const int m  = blockIdx.x >> 2;      // unit-group 0..31
    const int ks = blockIdx.x & 3;       // K-quarter
    const int kbase = ks * 256;
    const int j0 = m * 32;

    const u32 a_r  = (u32)(lane & 15);
    const u32 a_c8 = (u32)((lane >> 4) << 3);
    const u32 b_r  = (u32)(((lane >> 4) << 3) + (lane & 7));
    const u32 b_c8 = (u32)(((lane >> 3) & 1) << 3);

    float* Pmine = partial + (size_t)(ks * 32 + m) * 16384;

    for (int t = 0; t < 512; t++) {
        if (t > 0) {
            float acc[4][4][4];
#pragma unroll
            for (int a = 0; a < 4; a++)
#pragma unroll
                for (int b = 0; b < 4; b++)
#pragma unroll
                    for (int e = 0; e < 4; e++) acc[a][b][e] = 0.0f;

            ls_fill(sbase, Whi, Wlo, hhi, hlo, m, kbase, t - 1, tid);
            CPCOMMIT();

            for (int c = 0; c < 4; c++) {
                if (c < 3) {
                    ls_fill(sbase + ((c + 1) & 1) * LSB_BUF, Whi, Wlo, hhi, hlo,
                            m, kbase + (c + 1) * 64, t - 1, tid);
                    CPCOMMIT();
                    CPWAIT(1);
                } else {
                    CPWAIT(0);
                }
                __syncthreads();

                const u32 ab = sbase + (c & 1) * LSB_BUF;
#pragma unroll
                for (int kk = 0; kk < 4; kk++) {
                    const u32 kc = (u32)(kk * 16);
                    u32 baddr = ab + 2 * LSB_PL + (wc * 32 + b_r) * LSB_PITCH + (kc + b_c8) * 2;
                    u32 bh0[4], bh1[4], bl0[4], bl1[4];
                    ldsm4(baddr, bh0);
                    ldsm4(baddr + 16 * LSB_PITCH, bh1);
                    ldsm4(baddr + LSB_PL, bl0);
                    ldsm4(baddr + LSB_PL + 16 * LSB_PITCH, bl1);
#pragma unroll
                    for (int mb = 0; mb < 4; mb++) {
                        u32 aaddr = ab + (wr * 64 + mb * 16 + a_r) * LSB_PITCH + (kc + a_c8) * 2;
                        u32 ah[4], al[4];
                        ldsm4(aaddr, ah);
                        ldsm4(aaddr + LSB_PL, al);
                        mma16816(acc[mb][0], ah, bh0[0], bh0[1]);
                        mma16816(acc[mb][1], ah, bh0[2], bh0[3]);
                        mma16816(acc[mb][2], ah, bh1[0], bh1[1]);
                        mma16816(acc[mb][3], ah, bh1[2], bh1[3]);
                        mma16816(acc[mb][0], ah, bl0[0], bl0[1]);
                        mma16816(acc[mb][1], ah, bl0[2], bl0[3]);
                        mma16816(acc[mb][2], ah, bl1[0], bl1[1]);
                        mma16816(acc[mb][3], ah, bl1[2], bl1[3]);
                        mma16816(acc[mb][0], al, bh0[0], bh0[1]);
                        mma16816(acc[mb][1], al, bh0[2], bh0[3]);
                        mma16816(acc[mb][2], al, bh1[0], bh1[1]);
                        mma16816(acc[mb][3], al, bh1[2], bh1[3]);
                    }
                }
                __syncthreads();
            }

            // spill partial D tile: Pmine[row 128][batch 128]
#pragma unroll
            for (int nb = 0; nb < 4; nb++) {
                int n = wc * 32 + nb * 8 + (lane & 3) * 2;
#pragma unroll
                for (int mb = 0; mb < 4; mb++) {
                    int row = wr * 64 + mb * 16 + (lane >> 2);
                    *(float2*)(Pmine + row * 128 + n) =
                        make_float2(acc[mb][nb][0], acc[mb][nb][1]);
                    *(float2*)(Pmine + (row + 8) * 128 + n) =
                        make_float2(acc[mb][nb][2], acc[mb][nb][3]);
                }
            }
        }

        grid_barrier(LSTM_NBLK);     // partials visible

        if (t > 0) {
            // stage the 4 k-partials for (m, batch quarter ks) into smem
            // Ps[k][row 128][36 words] (data in words 0..31) — L1-bypass.
#pragma unroll
            for (int e = 0; e < 16; e++) {
                int idx = tid + e * 256;             // 0..4095
                int k = idx >> 10;
                int row = (idx >> 3) & 127;
                int seg = idx & 7;
                const float* src = partial + (size_t)(k * 32 + m) * 16384 +
                                   row * 128 + ks * 32 + seg * 4;
                CPASYNC_CG(sbase + PS_OFF + k * PS_K + row * LSB_PITCH + seg * 16, src);
            }
            CPCOMMIT();
            CPWAIT(0);
            __syncthreads();
        }

        // gate pass: 1024 items = 32 units x 32 batches (quarter), 4/thread
#pragma unroll
        for (int e = 0; e < 4; e++) {
            int u  = (lane & 7) + (e & 1) * 8 + (w & 1) * 16;
            int bl = (lane >> 3) + ((e >> 1) & 1) * 4 + (w >> 1) * 8;
            int b = ks * 32 + bl;
            size_t row = (size_t)b * 512 + t;
            const float* xr = xg + row * 4096 + j0 + u;
            float pa[4];
#pragma unroll
            for (int q = 0; q < 4; q++) {
                float s = xr[q * 1024];
                if (t > 0) {
#pragma unroll
                    for (int k = 0; k < 4; k++)
                        s += Ps[k * 4608 + (q * 32 + u) * 36 + bl];
                }
                pa[q] = s;
            }
            float cp = (t > 0) ? cs[u * 36 + bl] : 0.0f;
            float ig = 1.0f / (1.0f + expf(-pa[0]));
            float fg = 1.0f / (1.0f + expf(-pa[1]));
            float gv = tanhf(pa[2]);
            float og = 1.0f / (1.0f + expf(-pa[3]));
            float cn = fg * cp + ig * gv;
            float hv = og * tanhf(cn);
            cs[u * 36 + bl] = cn;
            hseq[row * 1024 + j0 + u] = hv;
            __nv_bfloat16 hb = __float2bfloat16(hv);
            hhi[row * 1024 + j0 + u] = hb;
            hlo[row * 1024 + j0 + u] =
                __float2bfloat16(hv - __bfloat162float(hb));
        }

        grid_barrier(LSTM_NBLK);     // h(t) visible before step t+1 fills
    }
}

// ===========================================================================
// Launch sequence, graph-capturable, allocation-free.
// ===========================================================================
extern "C" void kernel_launch(void* const* d_in, const int* in_sizes, int n_in,
                              void* d_out, int out_size)
{
    const float* input = (const float*)d_in[0];
    const float* W_ih0 = (const float*)d_in[1];
    const float* W_hh0 = (const float*)d_in[2];
    const float* b_ih0 = (const float*)d_in[3];
    const float* b_hh0 = (const float*)d_in[4];
    const float* W_ih1 = (const float*)d_in[5];
    const float* W_hh1 = (const float*)d_in[6];
    const float* b_ih1 = (const float*)d_in[7];
    const float* b_hh1 = (const float*)d_in[8];
    const float* W_fc  = (const float*)d_in[9];
    const float* b_fc  = (const float*)d_in[10];
    float* out = (float*)d_out;

    float *xg, *h, *part;
    __nv_bfloat16 *whh0hi, *whh0lo, *whh1hi, *whh1lo;
    __nv_bfloat16 *wihhi, *wihlo, *inhi, *inlo, *hshi, *hslo;
    cudaGetSymbolAddress((void**)&xg,     g_xg);
    cudaGetSymbolAddress((void**)&h,      g_h);
    cudaGetSymbolAddress((void**)&part,   g_partial);
    cudaGetSymbolAddress((void**)&whh0hi, g_whh0_hi);
    cudaGetSymbolAddress((void**)&whh0lo, g_whh0_lo);
    cudaGetSymbolAddress((void**)&whh1hi, g_whh1_hi);
    cudaGetSymbolAddress((void**)&whh1lo, g_whh1_lo);
    cudaGetSymbolAddress((void**)&wihhi,  g_wih_hi);
    cudaGetSymbolAddress((void**)&wihlo,  g_wih_lo);
    cudaGetSymbolAddress((void**)&inhi,   g_in_hi);
    cudaGetSymbolAddress((void**)&inlo,   g_in_lo);
    cudaGetSymbolAddress((void**)&hshi,   g_hs_hi);
    cudaGetSymbolAddress((void**)&hslo,   g_hs_lo);

    cudaFuncSetAttribute(gemm_tc,  cudaFuncAttributeMaxDynamicSharedMemorySize, GT_SMEM);
    cudaFuncSetAttribute(lstm_mma, cudaFuncAttributeMaxDynamicSharedMemorySize, LS_SMEM);

    // Prep
    split_plane<<<4096, 256>>>(input, inhi, inlo);
    split_plane<<<256, 256>>>(W_ih0, wihhi, wihlo);
    split_w32<<<4096, 256>>>(W_hh0, whh0hi, whh0lo);
    split_w32<<<4096, 256>>>(W_hh1, whh1hi, whh1lo);

    // Layer 0
    {
        dim3 g(4096 / 128, 65536 / 128);
        gemm_tc<<<g, 256, GT_SMEM>>>(inhi, inlo, wihhi, wihlo,
                                     b_ih0, b_hh0, xg, 4096, 64);
    }
    lstm_mma<<<LSTM_NBLK, 256, LS_SMEM>>>(xg, h, part, whh0hi, whh0lo,
                                          hshi, hslo);
    // Layer 1
    split_plane<<<4096, 256>>>(W_ih1, wihhi, wihlo);
    {
        dim3 g(4096 / 128, 65536 / 128);
        gemm_tc<<<g, 256, GT_SMEM>>>(hshi, hslo, wihhi, wihlo,
                                     b_ih1, b_hh1, xg, 4096, 1024);
    }
    lstm_mma<<<LSTM_NBLK, 256, LS_SMEM>>>(xg, h, part, whh1hi, whh1lo,
                                          hshi, hslo);

    // FC
    dim3 gf(1, 512);
    gemm_bias<<<gf, 256>>>(h, W_fc, b_fc, nullptr, out, 64, 1024);
}